// round 15
// baseline (speedup 1.0000x reference)
#include <cuda_runtime.h>
#include <math.h>

// Problem dims
#define BB   64
#define TT   512
#define DIN  64
#define DM   512
#define DOUT 64

// 128 CTAs = 4 row-blocks x 32 col-blocks, 1024 threads each (32 warps).
#define NCTA 128
#define NTHR 1024
#define RB   16
#define CB   16
#define AST  16   // h-activation smem row stride (64B rows)
#define WST  16   // weight smem row stride
#define RS   18   // reduction array output-row stride

// Transposed ping-pong hidden state in global: [k][batch-row], .cg only.
__device__ float g_h0T[2][DM * BB];
__device__ float g_h1T[2][DM * BB];
// Precomputed layer-0 input term, CTA-private slices:
// g_pre[cta][t][c_local*16 + r_local] = x(t)@Wih0 + bih0 + bhh0 for this CTA's
// 16 cols x 16 rows. 64MB, DRAM-resident, read 1KB/step/CTA (prefetched).
__device__ float g_pre[(size_t)NCTA * TT * 256];
// Epoch-parity barrier flags, scoped per row-block group (32 CTAs).
__device__ unsigned g_flags[2][4][32];

struct __align__(16) Smem {
    float  sAT[DM][AST];      // h0(t), transposed [k][row]
    float  sBT[DM][AST];      // h1(t-1), transposed
    float  whh0T[DM][WST];    // weight col-slices [k][col]
    float  wih1T[DM][WST];
    float  whh1T[DM][WST];
    float  w0s[DIN][16];      // Wih0 slice (prepass only)
    float2 woutT[DM];         // 2 output columns of Wout
    float  redB[16][CB * RS]; // layer-1 partials (32 k-groups pair-merged)
    float  redA[16][CB * RS]; // layer-0 partials
    float2 redo[32][17];      // out-GEMM partials [kgroup][row]
    float  cb0[CB], cb1[CB];
    float2 cbo;
};

// Fast tanh via __expf (MUFU-based): max err ~1e-6, handles +/-inf saturation.
__device__ __forceinline__ float ftanh(float x) {
    float e = __expf(2.f * x);
    return 1.f - __fdividef(2.f, e + 1.f);
}

// ---- L2-direct (L1-bypass) accessors ----
__device__ __forceinline__ float ldcg(const float *p) {
    float v;
    asm volatile("ld.global.cg.f32 %0, [%1];" : "=f"(v) : "l"(p));
    return v;
}
__device__ __forceinline__ void ldcg4(const float *p, float4 &v) {
    asm volatile("ld.global.cg.v4.f32 {%0,%1,%2,%3}, [%4];"
                 : "=f"(v.x), "=f"(v.y), "=f"(v.z), "=f"(v.w)
                 : "l"(p));
}
__device__ __forceinline__ void stcg(float *p, float v) {
    asm volatile("st.global.cg.f32 [%0], %1;" ::"l"(p), "f"(v));
}

// ---- barrier primitives: CG-style release/acquire, no CCTL.IVALL ----
__device__ __forceinline__ void flag_arrive(unsigned e, int rb, int cb) {
    asm volatile("st.release.gpu.u32 [%0], %1;" ::"l"(&g_flags[e & 1u][rb][cb]),
                 "r"(e)
                 : "memory");
}
__device__ __forceinline__ void flag_wait(unsigned e, int rb, int lane) {
    unsigned v;
    do {
        asm volatile("ld.acquire.gpu.u32 %0, [%1];"
                     : "=r"(v)
                     : "l"(&g_flags[e & 1u][rb][lane])
                     : "memory");
    } while (!__all_sync(0xffffffffu, v == e));
}

// ---- packed f32x2 helpers (Blackwell FFMA2) ----
__device__ __forceinline__ unsigned long long pack2(float lo, float hi) {
    unsigned long long r;
    asm("mov.b64 %0, {%1, %2};" : "=l"(r) : "f"(lo), "f"(hi));
    return r;
}
__device__ __forceinline__ void unpack2(unsigned long long v, float &lo, float &hi) {
    asm("mov.b64 {%0, %1}, %2;" : "=f"(lo), "=f"(hi) : "l"(v));
}
__device__ __forceinline__ void fma2(unsigned long long &d, unsigned long long a,
                                     unsigned long long b) {
    asm("fma.rn.f32x2 %0, %1, %2, %0;" : "+l"(d) : "l"(a), "l"(b));
}
__device__ __forceinline__ unsigned long long add2(unsigned long long a,
                                                   unsigned long long b) {
    unsigned long long r;
    asm("add.rn.f32x2 %0, %1, %2;" : "=l"(r) : "l"(a), "l"(b));
    return r;
}

// 2-row x 4-col tile, 32-way k-split with ks = warp id: every smem access has
// warp-uniform k (w LDS.128 = 4-address broadcast, a LDS.64 covers 16 banks).
template <bool FUSE>
__device__ __forceinline__ void gemm_rc(const float *__restrict__ aT,
                                        const float *__restrict__ w1T,
                                        const float *__restrict__ w2T, int ks,
                                        int r2, int c4,
                                        unsigned long long accB[2][2],
                                        unsigned long long accA[2][2]) {
#pragma unroll 4
    for (int i = 0; i < 16; i++) {
        int k = i * 32 + ks;
        unsigned long long av = *(const unsigned long long *)&aT[k * AST + r2];
        ulonglong2 w1 = *(const ulonglong2 *)&w1T[k * WST + c4];
        float ax, ay;
        unpack2(av, ax, ay);
        unsigned long long a0 = pack2(ax, ax);
        unsigned long long a1 = pack2(ay, ay);
        fma2(accB[0][0], a0, w1.x);
        fma2(accB[0][1], a0, w1.y);
        fma2(accB[1][0], a1, w1.x);
        fma2(accB[1][1], a1, w1.y);
        if (FUSE) {
            ulonglong2 w2 = *(const ulonglong2 *)&w2T[k * WST + c4];
            fma2(accA[0][0], a0, w2.x);
            fma2(accA[0][1], a0, w2.y);
            fma2(accA[1][0], a1, w2.x);
            fma2(accA[1][1], a1, w2.y);
        }
    }
}

// Warps 0-15: write partials (as packed 64-bit stores).
__device__ __forceinline__ void scatter(float (*__restrict__ red)[CB * RS],
                                        unsigned long long acc[2][2], int slot,
                                        int r2, int c4) {
#pragma unroll
    for (int r = 0; r < 2; r++)
#pragma unroll
        for (int cp = 0; cp < 2; cp++)
            *(unsigned long long *)&red[slot][(r2 + r) * RS + c4 + 2 * cp] =
                acc[r][cp];
}

// Warps 16-31: merge-add their k-group (same cell touched by exactly one
// thread -> race-free).
__device__ __forceinline__ void mergeAdd(float (*__restrict__ red)[CB * RS],
                                         unsigned long long acc[2][2], int slot,
                                         int r2, int c4) {
#pragma unroll
    for (int r = 0; r < 2; r++)
#pragma unroll
        for (int cp = 0; cp < 2; cp++) {
            unsigned long long *p =
                (unsigned long long *)&red[slot][(r2 + r) * RS + c4 + 2 * cp];
            *p = add2(*p, acc[r][cp]);
        }
}

// Final reduce: conflict-free red reads; coalesced stores to transposed h.
__device__ __forceinline__ void finalReduceH(const float (*__restrict__ red)[CB * RS],
                                             float bias, float *__restrict__ gdstT,
                                             int o, int r0, int c0) {
    int orr = o & 15, oc = o >> 4;
    float s = bias;
#pragma unroll
    for (int j = 0; j < 16; j++) s += red[j][orr * RS + oc];
    stcg(&gdstT[(c0 + oc) * BB + r0 + orr], ftanh(s));
}

// Staging from transposed global h: 2 x (LDG.128.cg + STS.128) per thread.
__device__ __forceinline__ void stageH(float (*__restrict__ dst)[AST],
                                       const float *__restrict__ srcT, int r0,
                                       int tid) {
#pragma unroll
    for (int it = 0; it < 2; it++) {
        int task = it * NTHR + tid;  // 0..2047
        int k = task >> 2, rg = (task & 3) << 2;
        float4 v;
        ldcg4(&srcT[k * BB + r0 + rg], v);
        *(float4 *)&dst[k][rg] = v;
    }
}

// out-GEMM: k = (2i+half)*32 + wid; pair-shuffle merges lane halves.
__device__ __forceinline__ void out_partial(Smem &S, int wid, int lane) {
    int row = lane & 15;
    int half = lane >> 4;
    unsigned long long o0 = pack2(0.f, 0.f), o1 = pack2(0.f, 0.f);
#pragma unroll
    for (int i = 0; i < 8; i++) {
        int k = (2 * i + half) * 32 + wid;
        float av = S.sBT[k][row];
        unsigned long long w = *(const unsigned long long *)&S.woutT[k];
        fma2((i & 1) ? o1 : o0, pack2(av, av), w);
    }
    unsigned long long tot = add2(o0, o1);
    tot = add2(tot, __shfl_xor_sync(0xffffffffu, tot, 16));
    if (lane < 16) {
        float x, y;
        unpack2(tot, x, y);
        S.redo[wid][row] = make_float2(x, y);
    }
}

__global__ void __launch_bounds__(NTHR, 1)
rnn_persistent_kernel(const float *__restrict__ data, const float *__restrict__ Wih0,
                      const float *__restrict__ bih0, const float *__restrict__ Whh0,
                      const float *__restrict__ bhh0, const float *__restrict__ Wih1,
                      const float *__restrict__ bih1, const float *__restrict__ Whh1,
                      const float *__restrict__ bhh1, const float *__restrict__ Wout,
                      const float *__restrict__ bout, float *__restrict__ out) {
    extern __shared__ char smem_raw[];
    Smem &S = *reinterpret_cast<Smem *>(smem_raw);

    const int tid = threadIdx.x;
    const int cta = blockIdx.x;
    const int rb = cta >> 5;
    const int cb = cta & 31;
    const int r0 = rb * RB;
    const int c0 = cb * CB;
    const int oc0 = cb * 2;
    const int wid = tid >> 5;
    const int lane = tid & 31;
    const int ks = wid;              // 32-way k-split (warp-uniform)
    const int slot = wid & 15;       // reduction slot (pair-merged)
    const bool writer = (wid < 16);
    const int r2 = (lane >> 2) * 2;
    const int c4 = (lane & 3) * 4;
    float *preCta = &g_pre[(size_t)cta * TT * 256];

    // ---- one-time: weights -> smem ----
    for (int idx = tid; idx < DM * 16; idx += NTHR) {
        int k = idx >> 4, c = idx & 15;
        S.whh0T[k][c] = Whh0[k * DM + c0 + c];
        S.wih1T[k][c] = Wih1[k * DM + c0 + c];
        S.whh1T[k][c] = Whh1[k * DM + c0 + c];
    }
    if (tid < DIN * 16) {
        int k = tid >> 4, c = tid & 15;
        S.w0s[k][c] = Wih0[k * DM + c0 + c];
    }
    for (int k = tid; k < DM; k += NTHR)
        S.woutT[k] = *(const float2 *)&Wout[k * DOUT + oc0];
    if (tid < CB) {
        S.cb0[tid] = bih0[c0 + tid] + bhh0[c0 + tid];
        S.cb1[tid] = bih1[c0 + tid] + bhh1[c0 + tid];
    }
    if (tid == 0) S.cbo = make_float2(bout[oc0], bout[oc0 + 1]);
    __syncthreads();

    // ---- prepass: pre[t] = x(t)@Wih0 + bih0 + bhh0 for this CTA's slice ----
    // Warp wid handles t in [wid*16, wid*16+16). Lane: r = lane&15, ch = lane>>4
    // covers cols ch*8..ch*8+7.
    {
        int r = lane & 15, ch = lane >> 4;
        for (int i = 0; i < 16; i++) {
            int t = wid * 16 + i;
            const float *xrow = &data[((size_t)(r0 + r) * TT + t) * DIN];
            unsigned long long acc[4];
            acc[0] = acc[1] = acc[2] = acc[3] = pack2(0.f, 0.f);
#pragma unroll 4
            for (int kq = 0; kq < 16; kq++) {
                float4 xv = *(const float4 *)&xrow[kq * 4];
                float xa[4] = {xv.x, xv.y, xv.z, xv.w};
#pragma unroll
                for (int j = 0; j < 4; j++) {
                    const float *wr = &S.w0s[kq * 4 + j][ch * 8];
                    ulonglong2 wa = *(const ulonglong2 *)wr;
                    ulonglong2 wb = *(const ulonglong2 *)(wr + 4);
                    unsigned long long xx = pack2(xa[j], xa[j]);
                    fma2(acc[0], xx, wa.x);
                    fma2(acc[1], xx, wa.y);
                    fma2(acc[2], xx, wb.x);
                    fma2(acc[3], xx, wb.y);
                }
            }
            float *dst = &preCta[(size_t)t * 256];
#pragma unroll
            for (int cp = 0; cp < 4; cp++) {
                float x0, x1;
                unpack2(acc[cp], x0, x1);
                int c = ch * 8 + 2 * cp;
                stcg(&dst[c * 16 + r], x0 + S.cb0[c]);
                stcg(&dst[(c + 1) * 16 + r], x1 + S.cb0[c + 1]);
            }
        }
    }
    __syncthreads();

    // ---- prologue: h0(0) = tanh(pre[0]) (CTA-private, no barrier needed) ----
    if (tid < 256) {
        float p = ldcg(&preCta[tid]);
        stcg(&g_h0T[0][(c0 + (tid >> 4)) * BB + r0 + (tid & 15)], ftanh(p));
    }

    unsigned epoch = 1;
    __syncthreads();
    if (tid == 0) flag_arrive(epoch, rb, cb);
    flag_wait(epoch, rb, lane);  // all warps wait independently

#pragma unroll 1
    for (int t = 0; t < TT; t++) {
        // Register-prefetch this iteration's layer-0 pre term (DRAM latency
        // hidden under staging + GEMM).
        float pf = 0.f;
        if (tid >= 256 && tid < 512) {
            int tn = (t + 1 < TT) ? t + 1 : TT - 1;
            pf = ldcg(&preCta[(size_t)tn * 256 + (tid - 256)]);
        }
        // Buffers: h0(t) in g_h0T[t&1]; h1(t-1) in g_h1T[(t+1)&1].
        // Writes h1(t) -> g_h1T[t&1], h0(t+1) -> g_h0T[(t+1)&1].
        stageH(S.sAT, g_h0T[t & 1], r0, tid);
        if (t > 0) stageH(S.sBT, g_h1T[(t + 1) & 1], r0, tid);
        __syncthreads();

        unsigned long long accB[2][2], accA[2][2];
        accB[0][0] = accB[0][1] = accB[1][0] = accB[1][1] = pack2(0.f, 0.f);
        accA[0][0] = accA[0][1] = accA[1][0] = accA[1][1] = pack2(0.f, 0.f);

        // Fused over sAT: accB += sAT@Wih1, accA += sAT@Whh0 (shared a-loads)
        gemm_rc<true>(&S.sAT[0][0], &S.wih1T[0][0], &S.whh0T[0][0], ks, r2, c4,
                      accB, accA);
        // accB += h1(t-1)@Whh1
        if (t > 0) {
            unsigned long long dummy[2][2];
            gemm_rc<false>(&S.sBT[0][0], &S.whh1T[0][0], nullptr, ks, r2, c4, accB,
                           dummy);
        }
        // out(t-1) partials from h1(t-1) (in sBT)
        if (t > 0) out_partial(S, wid, lane);

        // two-round k-reduction: scatter (warps 0-15) then merge (16-31)
        if (writer) {
            scatter(S.redB, accB, slot, r2, c4);
            scatter(S.redA, accA, slot, r2, c4);
        }
        __syncthreads();
        if (!writer) {
            mergeAdd(S.redB, accB, slot, r2, c4);
            mergeAdd(S.redA, accA, slot, r2, c4);
        }
        __syncthreads();

        // final reduces: threads 0-255 layer-1, 256-511 layer-0 (pre term)
        if (tid < 256) {
            finalReduceH(S.redB, S.cb1[tid >> 4], g_h1T[t & 1], tid, r0, c0);
        } else if (tid < 512) {
            finalReduceH(S.redA, pf, g_h0T[(t + 1) & 1], tid - 256, r0, c0);
        }

        // barrier; out(t-1) store hidden between arrive and wait (warp 0)
        epoch++;
        __syncthreads();
        if (tid == 0) flag_arrive(epoch, rb, cb);
        if (wid == 0 && t > 0 && lane < 16) {
            float s0 = S.cbo.x, s1 = S.cbo.y;
#pragma unroll
            for (int j = 0; j < 32; j++) {
                float2 p = S.redo[j][lane];
                s0 += p.x;
                s1 += p.y;
            }
            *(float2 *)&out[((r0 + lane) * TT + (t - 1)) * DOUT + oc0] =
                make_float2(s0, s1);
        }
        flag_wait(epoch, rb, lane);  // all warps; no trailing __syncthreads
    }

    // ---- epilogue: out(T-1) from h1(T-1) in g_h1T[1] ----
    stageH(S.sBT, g_h1T[1], r0, tid);
    __syncthreads();
    out_partial(S, wid, lane);
    __syncthreads();
    if (tid < 16) {
        float s0 = S.cbo.x, s1 = S.cbo.y;
#pragma unroll
        for (int j = 0; j < 32; j++) {
            float2 p = S.redo[j][tid];
            s0 += p.x;
            s1 += p.y;
        }
        *(float2 *)&out[((r0 + tid) * TT + (TT - 1)) * DOUT + oc0] =
            make_float2(s0, s1);
    }
}

extern "C" void kernel_launch(void *const *d_in, const int *in_sizes, int n_in,
                              void *d_out, int out_size) {
    const float *data = (const float *)d_in[0];
    const float *Wih0 = (const float *)d_in[1];
    const float *bih0 = (const float *)d_in[2];
    const float *Whh0 = (const float *)d_in[3];
    const float *bhh0 = (const float *)d_in[4];
    const float *Wih1 = (const float *)d_in[5];
    const float *bih1 = (const float *)d_in[6];
    const float *Whh1 = (const float *)d_in[7];
    const float *bhh1 = (const float *)d_in[8];
    const float *Wout = (const float *)d_in[9];
    const float *bout = (const float *)d_in[10];
    float *out = (float *)d_out;

    cudaFuncSetAttribute(rnn_persistent_kernel,
                         cudaFuncAttributeMaxDynamicSharedMemorySize,
                         (int)sizeof(Smem));

    rnn_persistent_kernel<<<NCTA, NTHR, sizeof(Smem)>>>(
        data, Wih0, bih0, Whh0, bhh0, Wih1, bih1, Whh1, bhh1, Wout, bout, out);
}

// round 16
// speedup vs baseline: 2.3962x; 2.3962x over previous
#include <cuda_runtime.h>
#include <math.h>

// Problem dims
#define BB   64
#define TT   512
#define DIN  64
#define DM   512
#define DOUT 64

// 128 CTAs = 4 row-blocks x 32 col-blocks, 1024 threads each (32 warps).
#define NCTA 128
#define NTHR 1024
#define RB   16
#define CB   16
#define AST  16   // h-activation smem row stride (64B rows)
#define WST  16   // weight smem row stride
#define RS   18   // reduction array output-row stride

// Transposed ping-pong hidden state in global: [k][batch-row], .cg only.
__device__ float g_h0T[2][DM * BB];
__device__ float g_h1T[2][DM * BB];
// Precomputed layer-0 input term, CTA-private slices:
// g_pre[cta][t][c_local*16 + r_local] = x(t)@Wih0 + bih0 + bhh0.
__device__ float g_pre[(size_t)NCTA * TT * 256];
// Epoch-parity barrier flags, scoped per row-block group (32 CTAs).
__device__ unsigned g_flags[2][4][32];

struct __align__(16) Smem {
    float  sAT[DM][AST];      // h0(t), transposed [k][row]
    float  sBT[DM][AST];      // h1(t-1), transposed
    float  whh0T[DM][WST];    // weight col-slices [k][col]
    float  wih1T[DM][WST];
    float  whh1T[DM][WST];
    float  w0s[DIN][16];      // Wih0 slice (prepass only)
    float2 woutT[DM];         // 2 output columns of Wout
    float  redB[16][CB * RS]; // layer-1 partials (32 k-groups pair-merged)
    float  redA[16][CB * RS]; // layer-0 partials
    float2 redo[32][17];      // out-GEMM partials [kgroup][row]
    float  cb0[CB], cb1[CB];
    float2 cbo;
};

// Fast tanh via __expf (MUFU-based): max err ~1e-6, saturates correctly.
__device__ __forceinline__ float ftanh(float x) {
    float e = __expf(2.f * x);
    return 1.f - __fdividef(2.f, e + 1.f);
}

// ---- L2-direct (L1-bypass) accessors ----
__device__ __forceinline__ float ldcg(const float *p) {
    float v;
    asm volatile("ld.global.cg.f32 %0, [%1];" : "=f"(v) : "l"(p));
    return v;
}
__device__ __forceinline__ void ldcg4(const float *p, float4 &v) {
    asm volatile("ld.global.cg.v4.f32 {%0,%1,%2,%3}, [%4];"
                 : "=f"(v.x), "=f"(v.y), "=f"(v.z), "=f"(v.w)
                 : "l"(p));
}
__device__ __forceinline__ void stcg(float *p, float v) {
    asm volatile("st.global.cg.f32 [%0], %1;" ::"l"(p), "f"(v));
}

// ---- barrier primitives: CG-style release/acquire; ONLY warp 0 polls ----
__device__ __forceinline__ void flag_arrive(unsigned e, int rb, int cb) {
    asm volatile("st.release.gpu.u32 [%0], %1;" ::"l"(&g_flags[e & 1u][rb][cb]),
                 "r"(e)
                 : "memory");
}
__device__ __forceinline__ void flag_wait(unsigned e, int rb, int lane) {
    unsigned v;
    do {  // 32 consecutive u32 flags -> one coalesced 128B probe per round
        asm volatile("ld.acquire.gpu.u32 %0, [%1];"
                     : "=r"(v)
                     : "l"(&g_flags[e & 1u][rb][lane])
                     : "memory");
    } while (!__all_sync(0xffffffffu, v == e));
}

// ---- packed f32x2 helpers (Blackwell FFMA2) ----
__device__ __forceinline__ unsigned long long pack2(float lo, float hi) {
    unsigned long long r;
    asm("mov.b64 %0, {%1, %2};" : "=l"(r) : "f"(lo), "f"(hi));
    return r;
}
__device__ __forceinline__ void unpack2(unsigned long long v, float &lo, float &hi) {
    asm("mov.b64 {%0, %1}, %2;" : "=f"(lo), "=f"(hi) : "l"(v));
}
__device__ __forceinline__ void fma2(unsigned long long &d, unsigned long long a,
                                     unsigned long long b) {
    asm("fma.rn.f32x2 %0, %1, %2, %0;" : "+l"(d) : "l"(a), "l"(b));
}
__device__ __forceinline__ unsigned long long add2(unsigned long long a,
                                                   unsigned long long b) {
    unsigned long long r;
    asm("add.rn.f32x2 %0, %1, %2;" : "=l"(r) : "l"(a), "l"(b));
    return r;
}

// 2-row x 4-col tile, 32-way k-split with ks = warp id: warp-uniform k, so
// the weight LDS.128 is a 4-address broadcast and a LDS.64 spans 16 banks.
template <bool FUSE>
__device__ __forceinline__ void gemm_rc(const float *__restrict__ aT,
                                        const float *__restrict__ w1T,
                                        const float *__restrict__ w2T, int ks,
                                        int r2, int c4,
                                        unsigned long long accB[2][2],
                                        unsigned long long accA[2][2]) {
#pragma unroll 4
    for (int i = 0; i < 16; i++) {
        int k = i * 32 + ks;
        unsigned long long av = *(const unsigned long long *)&aT[k * AST + r2];
        ulonglong2 w1 = *(const ulonglong2 *)&w1T[k * WST + c4];
        float ax, ay;
        unpack2(av, ax, ay);
        unsigned long long a0 = pack2(ax, ax);
        unsigned long long a1 = pack2(ay, ay);
        fma2(accB[0][0], a0, w1.x);
        fma2(accB[0][1], a0, w1.y);
        fma2(accB[1][0], a1, w1.x);
        fma2(accB[1][1], a1, w1.y);
        if (FUSE) {
            ulonglong2 w2 = *(const ulonglong2 *)&w2T[k * WST + c4];
            fma2(accA[0][0], a0, w2.x);
            fma2(accA[0][1], a0, w2.y);
            fma2(accA[1][0], a1, w2.x);
            fma2(accA[1][1], a1, w2.y);
        }
    }
}

// Warps 0-15: write partials (packed 64-bit stores).
__device__ __forceinline__ void scatter(float (*__restrict__ red)[CB * RS],
                                        unsigned long long acc[2][2], int slot,
                                        int r2, int c4) {
#pragma unroll
    for (int r = 0; r < 2; r++)
#pragma unroll
        for (int cp = 0; cp < 2; cp++)
            *(unsigned long long *)&red[slot][(r2 + r) * RS + c4 + 2 * cp] =
                acc[r][cp];
}

// Warps 16-31: merge-add their k-group (each cell touched by one thread).
__device__ __forceinline__ void mergeAdd(float (*__restrict__ red)[CB * RS],
                                         unsigned long long acc[2][2], int slot,
                                         int r2, int c4) {
#pragma unroll
    for (int r = 0; r < 2; r++)
#pragma unroll
        for (int cp = 0; cp < 2; cp++) {
            unsigned long long *p =
                (unsigned long long *)&red[slot][(r2 + r) * RS + c4 + 2 * cp];
            *p = add2(*p, acc[r][cp]);
        }
}

// Final reduce: conflict-free red reads; coalesced stores to transposed h.
__device__ __forceinline__ void finalReduceH(const float (*__restrict__ red)[CB * RS],
                                             float bias, float *__restrict__ gdstT,
                                             int o, int r0, int c0) {
    int orr = o & 15, oc = o >> 4;
    float s = bias;
#pragma unroll
    for (int j = 0; j < 16; j++) s += red[j][orr * RS + oc];
    stcg(&gdstT[(c0 + oc) * BB + r0 + orr], ftanh(s));
}

// Staging from transposed global h: 2 x (LDG.128.cg + STS.128) per thread.
__device__ __forceinline__ void stageH(float (*__restrict__ dst)[AST],
                                       const float *__restrict__ srcT, int r0,
                                       int tid) {
#pragma unroll
    for (int it = 0; it < 2; it++) {
        int task = it * NTHR + tid;  // 0..2047
        int k = task >> 2, rg = (task & 3) << 2;
        float4 v;
        ldcg4(&srcT[k * BB + r0 + rg], v);
        *(float4 *)&dst[k][rg] = v;
    }
}

// out-GEMM: k = (2i+half)*32 + wid; pair-shuffle merges lane halves.
__device__ __forceinline__ void out_partial(Smem &S, int wid, int lane) {
    int row = lane & 15;
    int half = lane >> 4;
    unsigned long long o0 = pack2(0.f, 0.f), o1 = pack2(0.f, 0.f);
#pragma unroll
    for (int i = 0; i < 8; i++) {
        int k = (2 * i + half) * 32 + wid;
        float av = S.sBT[k][row];
        unsigned long long w = *(const unsigned long long *)&S.woutT[k];
        fma2((i & 1) ? o1 : o0, pack2(av, av), w);
    }
    unsigned long long tot = add2(o0, o1);
    tot = add2(tot, __shfl_xor_sync(0xffffffffu, tot, 16));
    if (lane < 16) {
        float x, y;
        unpack2(tot, x, y);
        S.redo[wid][row] = make_float2(x, y);
    }
}

__global__ void __launch_bounds__(NTHR, 1)
rnn_persistent_kernel(const float *__restrict__ data, const float *__restrict__ Wih0,
                      const float *__restrict__ bih0, const float *__restrict__ Whh0,
                      const float *__restrict__ bhh0, const float *__restrict__ Wih1,
                      const float *__restrict__ bih1, const float *__restrict__ Whh1,
                      const float *__restrict__ bhh1, const float *__restrict__ Wout,
                      const float *__restrict__ bout, float *__restrict__ out) {
    extern __shared__ char smem_raw[];
    Smem &S = *reinterpret_cast<Smem *>(smem_raw);

    const int tid = threadIdx.x;
    const int cta = blockIdx.x;
    const int rb = cta >> 5;
    const int cb = cta & 31;
    const int r0 = rb * RB;
    const int c0 = cb * CB;
    const int oc0 = cb * 2;
    const int wid = tid >> 5;
    const int lane = tid & 31;
    const int ks = wid;              // 32-way k-split (warp-uniform)
    const int slot = wid & 15;       // reduction slot (pair-merged)
    const bool writer = (wid < 16);
    const int r2 = (lane >> 2) * 2;
    const int c4 = (lane & 3) * 4;
    float *preCta = &g_pre[(size_t)cta * TT * 256];

    // ---- one-time: weights -> smem ----
    for (int idx = tid; idx < DM * 16; idx += NTHR) {
        int k = idx >> 4, c = idx & 15;
        S.whh0T[k][c] = Whh0[k * DM + c0 + c];
        S.wih1T[k][c] = Wih1[k * DM + c0 + c];
        S.whh1T[k][c] = Whh1[k * DM + c0 + c];
    }
    if (tid < DIN * 16) {
        int k = tid >> 4, c = tid & 15;
        S.w0s[k][c] = Wih0[k * DM + c0 + c];
    }
    for (int k = tid; k < DM; k += NTHR)
        S.woutT[k] = *(const float2 *)&Wout[k * DOUT + oc0];
    if (tid < CB) {
        S.cb0[tid] = bih0[c0 + tid] + bhh0[c0 + tid];
        S.cb1[tid] = bih1[c0 + tid] + bhh1[c0 + tid];
    }
    if (tid == 0) S.cbo = make_float2(bout[oc0], bout[oc0 + 1]);
    __syncthreads();

    // ---- prepass: pre[t] = x(t)@Wih0 + bih0 + bhh0 for this CTA's slice ----
    // Warp wid handles t in [wid*16, wid*16+16); lane r=lane&15, ch=lane>>4.
    {
        int r = lane & 15, ch = lane >> 4;
        for (int i = 0; i < 16; i++) {
            int t = wid * 16 + i;
            const float *xrow = &data[((size_t)(r0 + r) * TT + t) * DIN];
            unsigned long long acc[4];
            acc[0] = acc[1] = acc[2] = acc[3] = pack2(0.f, 0.f);
#pragma unroll 4
            for (int kq = 0; kq < 16; kq++) {
                float4 xv = *(const float4 *)&xrow[kq * 4];
                float xa[4] = {xv.x, xv.y, xv.z, xv.w};
#pragma unroll
                for (int j = 0; j < 4; j++) {
                    const float *wr = &S.w0s[kq * 4 + j][ch * 8];
                    ulonglong2 wa = *(const ulonglong2 *)wr;
                    ulonglong2 wb = *(const ulonglong2 *)(wr + 4);
                    unsigned long long xx = pack2(xa[j], xa[j]);
                    fma2(acc[0], xx, wa.x);
                    fma2(acc[1], xx, wa.y);
                    fma2(acc[2], xx, wb.x);
                    fma2(acc[3], xx, wb.y);
                }
            }
            float *dst = &preCta[(size_t)t * 256];
#pragma unroll
            for (int cp = 0; cp < 4; cp++) {
                float x0, x1;
                unpack2(acc[cp], x0, x1);
                int c = ch * 8 + 2 * cp;
                stcg(&dst[c * 16 + r], x0 + S.cb0[c]);
                stcg(&dst[(c + 1) * 16 + r], x1 + S.cb0[c + 1]);
            }
        }
    }
    __syncthreads();

    // ---- prologue: h0(0) = tanh(pre[0]) (CTA-private) ----
    if (tid < 256) {
        float p = ldcg(&preCta[tid]);
        stcg(&g_h0T[0][(c0 + (tid >> 4)) * BB + r0 + (tid & 15)], ftanh(p));
    }

    unsigned epoch = 1;
    __syncthreads();
    if (tid == 0) flag_arrive(epoch, rb, cb);
    if (tid < 32) flag_wait(epoch, rb, tid);
    __syncthreads();

#pragma unroll 1
    for (int t = 0; t < TT; t++) {
        // Register-prefetch the layer-0 pre term for h0(t+1) (hidden under
        // staging + GEMM).
        float pf = 0.f;
        if (tid >= 256 && tid < 512) {
            int tn = (t + 1 < TT) ? t + 1 : TT - 1;
            pf = ldcg(&preCta[(size_t)tn * 256 + (tid - 256)]);
        }
        // Buffers: h0(t) in g_h0T[t&1]; h1(t-1) in g_h1T[(t+1)&1].
        // Writes h1(t) -> g_h1T[t&1], h0(t+1) -> g_h0T[(t+1)&1].
        stageH(S.sAT, g_h0T[t & 1], r0, tid);
        if (t > 0) stageH(S.sBT, g_h1T[(t + 1) & 1], r0, tid);
        __syncthreads();

        unsigned long long accB[2][2], accA[2][2];
        accB[0][0] = accB[0][1] = accB[1][0] = accB[1][1] = pack2(0.f, 0.f);
        accA[0][0] = accA[0][1] = accA[1][0] = accA[1][1] = pack2(0.f, 0.f);

        // Fused over sAT: accB += sAT@Wih1, accA += sAT@Whh0 (shared a-loads)
        gemm_rc<true>(&S.sAT[0][0], &S.wih1T[0][0], &S.whh0T[0][0], ks, r2, c4,
                      accB, accA);
        // accB += h1(t-1)@Whh1
        if (t > 0) {
            unsigned long long dummy[2][2];
            gemm_rc<false>(&S.sBT[0][0], &S.whh1T[0][0], nullptr, ks, r2, c4, accB,
                           dummy);
        }
        // out(t-1) partials from h1(t-1) (in sBT)
        if (t > 0) out_partial(S, wid, lane);

        // two-round k-reduction: scatter (warps 0-15) then merge (16-31)
        if (writer) {
            scatter(S.redB, accB, slot, r2, c4);
            scatter(S.redA, accA, slot, r2, c4);
        }
        __syncthreads();
        if (!writer) {
            mergeAdd(S.redB, accB, slot, r2, c4);
            mergeAdd(S.redA, accA, slot, r2, c4);
        }
        __syncthreads();

        // final reduces: threads 0-255 layer-1, 256-511 layer-0 (pre term)
        if (tid < 256) {
            finalReduceH(S.redB, S.cb1[tid >> 4], g_h1T[t & 1], tid, r0, c0);
        } else if (tid < 512) {
            finalReduceH(S.redA, pf, g_h0T[(t + 1) & 1], tid - 256, r0, c0);
        }

        // barrier; out(t-1) store hidden between arrive and wait (warp 0 only
        // polls -> no chip-wide acquire storm)
        epoch++;
        __syncthreads();
        if (tid == 0) flag_arrive(epoch, rb, cb);
        if (tid < 32) {
            if (t > 0 && tid < 16) {
                float s0 = S.cbo.x, s1 = S.cbo.y;
#pragma unroll
                for (int j = 0; j < 32; j++) {
                    float2 p = S.redo[j][tid];
                    s0 += p.x;
                    s1 += p.y;
                }
                *(float2 *)&out[((r0 + tid) * TT + (t - 1)) * DOUT + oc0] =
                    make_float2(s0, s1);
            }
            flag_wait(epoch, rb, tid);
        }
        __syncthreads();
    }

    // ---- epilogue: out(T-1) from h1(T-1) in g_h1T[1] ----
    stageH(S.sBT, g_h1T[1], r0, tid);
    __syncthreads();
    out_partial(S, wid, lane);
    __syncthreads();
    if (tid < 16) {
        float s0 = S.cbo.x, s1 = S.cbo.y;
#pragma unroll
        for (int j = 0; j < 32; j++) {
            float2 p = S.redo[j][tid];
            s0 += p.x;
            s1 += p.y;
        }
        *(float2 *)&out[((r0 + tid) * TT + (TT - 1)) * DOUT + oc0] =
            make_float2(s0, s1);
    }
}

extern "C" void kernel_launch(void *const *d_in, const int *in_sizes, int n_in,
                              void *d_out, int out_size) {
    const float *data = (const float *)d_in[0];
    const float *Wih0 = (const float *)d_in[1];
    const float *bih0 = (const float *)d_in[2];
    const float *Whh0 = (const float *)d_in[3];
    const float *bhh0 = (const float *)d_in[4];
    const float *Wih1 = (const float *)d_in[5];
    const float *bih1 = (const float *)d_in[6];
    const float *Whh1 = (const float *)d_in[7];
    const float *bhh1 = (const float *)d_in[8];
    const float *Wout = (const float *)d_in[9];
    const float *bout = (const float *)d_in[10];
    float *out = (float *)d_out;

    cudaFuncSetAttribute(rnn_persistent_kernel,
                         cudaFuncAttributeMaxDynamicSharedMemorySize,
                         (int)sizeof(Smem));

    rnn_persistent_kernel<<<NCTA, NTHR, sizeof(Smem)>>>(
        data, Wih0, bih0, Whh0, bhh0, Wih1, bih1, Whh1, bhh1, Wout, bout, out);
}